// round 16
// baseline (speedup 1.0000x reference)
#include <cuda_runtime.h>
#include <cuda_fp16.h>
#include <cstdint>

#define BB 256
#define NN 512
#define EE 64
#define OO 64
#define KK 8
#define NSPLIT 8
#define NCHUNK (NN / NSPLIT)   // 64

// Scratch (static device allocations — allowed)
__device__ float  g_priors[BB * NN * OO];              // 33.5 MB
__device__ float  g_zpart[BB * NSPLIT * KK * OO];      // 4 MB
__device__ float  g_vacc[BB * KK * OO];                // 0.5 MB
// Shadow layout: [b][n][o][k] — 8 k-halves contiguous (16B) per (n,o).
__device__ __half g_shadow[(size_t)BB * NN * OO * KK]; // 134 MB

__device__ __forceinline__ float fast_ex2(float x) {
    float y; asm("ex2.approx.f32 %0, %1;" : "=f"(y) : "f"(x)); return y;
}
__device__ __forceinline__ float fast_rcp(float x) {
    float y; asm("rcp.approx.f32 %0, %1;" : "=f"(y) : "f"(x)); return y;
}
__device__ __forceinline__ uint32_t h2_bits(__half2 h) {
    uint32_t u; __builtin_memcpy(&u, &h, 4); return u;
}

// ---------------------------------------------------------------------------
// Iteration 1, FUSED with the priors GEMM. Writes zpart + fp16 shadow.
// ---------------------------------------------------------------------------
__global__ void __launch_bounds__(256, 5) route_first_kernel(
        const float* __restrict__ cc,
        const float* __restrict__ emb,
        const float* __restrict__ S) {
    __shared__ float buf0[64][68];   // sA (emb^T) -> ps (priors tile)
    __shared__ float buf1[64][68];   // sB (S)     -> reduction buffer

    const int t  = threadIdx.x;
    const int b  = blockIdx.x >> 3;
    const int sp = blockIdx.x & 7;
    const int n0 = sp * NCHUNK;

    // ---- Phase A: GEMM ----
    {
        const float* embBase = emb + ((size_t)b * NN + n0) * EE;
        #pragma unroll
        for (int i = t; i < 1024; i += 256) {
            int row = i >> 4;
            int e4  = (i & 15) << 2;
            float4 v = *(const float4*)(embBase + row * EE + e4);
            buf0[e4 + 0][row] = v.x; buf0[e4 + 1][row] = v.y;
            buf0[e4 + 2][row] = v.z; buf0[e4 + 3][row] = v.w;
        }
        #pragma unroll
        for (int i = t; i < 1024; i += 256) {
            int e  = i >> 4;
            int c4 = (i & 15) << 2;
            *(float4*)&buf1[e][c4] = *(const float4*)(S + e * OO + c4);
        }
        __syncthreads();

        const int tr = (t >> 4) << 2;
        const int tc = (t & 15) << 2;
        float acc[4][4];
        #pragma unroll
        for (int i = 0; i < 4; i++)
            #pragma unroll
            for (int j = 0; j < 4; j++) acc[i][j] = 0.f;

        #pragma unroll 8
        for (int e = 0; e < 64; e++) {
            float4 a = *(const float4*)&buf0[e][tr];
            float4 bq = *(const float4*)&buf1[e][tc];
            float av[4] = {a.x, a.y, a.z, a.w};
            float bv[4] = {bq.x, bq.y, bq.z, bq.w};
            #pragma unroll
            for (int i = 0; i < 4; i++)
                #pragma unroll
                for (int j = 0; j < 4; j++)
                    acc[i][j] = fmaf(av[i], bv[j], acc[i][j]);
        }
        __syncthreads();   // done reading sA before ps overwrites it

        float* outBase = g_priors + ((size_t)b * NN + n0) * OO;
        #pragma unroll
        for (int i = 0; i < 4; i++) {
            float4 v = make_float4(acc[i][0], acc[i][1], acc[i][2], acc[i][3]);
            *(float4*)&buf0[tr + i][tc] = v;                       // ps
            *(float4*)(outBase + (size_t)(tr + i) * OO + tc) = v;  // g_priors
        }
        __syncthreads();
    }

    // ---- Phase B: routing iteration 1 ----
    float (*ps)[68] = buf0;

    const int og   = t & 31;        // o-pair index
    const int ob   = og << 1;
    const int nrep = t >> 5;        // 8 n-replicas (one warp each)
    float acc[KK][2];
    #pragma unroll
    for (int k = 0; k < KK; k++) { acc[k][0] = 0.f; acc[k][1] = 0.f; }

    const float* ccBase = cc + ((size_t)b * KK * NN + n0) * OO + ob;
    __half*      shBase = g_shadow + (((size_t)b * NN + n0) * OO + ob) * KK;
    const float L2E = 1.4426950408889634f;

    #pragma unroll 2
    for (int n = nrep; n < NCHUNK; n += 8) {
        float c[KK][2];
        #pragma unroll
        for (int k = 0; k < KK; k++) {
            float2 c2 = __ldcs((const float2*)(ccBase + ((size_t)k * NN + n) * OO));
            c[k][0] = c2.x; c[k][1] = c2.y;
        }
        float2 p2 = *(const float2*)&ps[n][ob];
        float m0 = c[0][0], m1 = c[0][1];
        #pragma unroll
        for (int k = 1; k < KK; k++) {
            m0 = fmaxf(m0, c[k][0]);
            m1 = fmaxf(m1, c[k][1]);
        }
        m0 *= L2E; m1 *= L2E;
        float s0 = 0.f, s1 = 0.f;
        #pragma unroll
        for (int k = 0; k < KK; k++) {
            float e0 = fast_ex2(fmaf(c[k][0], L2E, -m0));
            float e1 = fast_ex2(fmaf(c[k][1], L2E, -m1));
            c[k][0] = e0; c[k][1] = e1;
            s0 += e0; s1 += e1;
        }
        {
            uint4 u0, u1;
            u0.x = h2_bits(__floats2half2_rn(c[0][0], c[1][0]));
            u0.y = h2_bits(__floats2half2_rn(c[2][0], c[3][0]));
            u0.z = h2_bits(__floats2half2_rn(c[4][0], c[5][0]));
            u0.w = h2_bits(__floats2half2_rn(c[6][0], c[7][0]));
            u1.x = h2_bits(__floats2half2_rn(c[0][1], c[1][1]));
            u1.y = h2_bits(__floats2half2_rn(c[2][1], c[3][1]));
            u1.z = h2_bits(__floats2half2_rn(c[4][1], c[5][1]));
            u1.w = h2_bits(__floats2half2_rn(c[6][1], c[7][1]));
            __half* dst = shBase + (size_t)n * OO * KK;
            __stcs((uint4*)dst, u0);
            __stcs((uint4*)(dst + KK), u1);
        }
        float pr0 = p2.x * fast_rcp(s0);
        float pr1 = p2.y * fast_rcp(s1);
        #pragma unroll
        for (int k = 0; k < KK; k++) {
            acc[k][0] = fmaf(c[k][0], pr0, acc[k][0]);
            acc[k][1] = fmaf(c[k][1], pr1, acc[k][1]);
        }
    }

    // Cross-warp reduction in buf1: red[(w*32 + og)*17 + kj], stride 17.
    float* red = &buf1[0][0];
    __syncthreads();
    {
        float* dst = red + (size_t)(nrep * 32 + og) * 17;
        #pragma unroll
        for (int k = 0; k < KK; k++) {
            dst[k * 2]     = acc[k][0];
            dst[k * 2 + 1] = acc[k][1];
        }
    }
    __syncthreads();

    #pragma unroll
    for (int id = t; id < 512; id += 256) {
        int og_ = id >> 4;
        int kj  = id & 15;
        float ssum = 0.f;
        #pragma unroll
        for (int w_ = 0; w_ < 8; w_++)
            ssum += red[(size_t)(w_ * 32 + og_) * 17 + kj];
        int k = kj >> 1;
        int j = kj & 1;
        int o = (og_ << 1) + j;
        g_zpart[(((size_t)b * NSPLIT + sp) * KK + k) * OO + o] = ssum;
    }
}

// ---------------------------------------------------------------------------
// Iterations 2..: read fp16 shadow E via ldcs, w ∝ E * exp(delta - max).
// 2 o's per thread; first n-step's shadow loads issued BEFORE the delta
// phase (cross-phase prefetch), hot loop is an explicit depth-1 pipeline.
// ---------------------------------------------------------------------------
__global__ void __launch_bounds__(256, 4) route_next_kernel() {
    __shared__ float ps[NCHUNK][68];   // priors chunk; reused as reduction buffer
    __shared__ float ds[NCHUNK][8];    // ed = exp(delta - rowmax)
    __shared__ float vs[KK][68];       // Vacc slice

    const int t  = threadIdx.x;
    const int b  = blockIdx.x >> 3;
    const int sp = blockIdx.x & 7;
    const int n0 = sp * NCHUNK;

    const int og   = t & 31;        // o-pair index
    const int ob   = og << 1;
    const int nrep = t >> 5;        // 8 n-replicas

    // Issue priors staging loads.
    const float* pBase = g_priors + ((size_t)b * NN + n0) * OO;
    #pragma unroll
    for (int i = t; i < NCHUNK * 16; i += 256) {
        int n  = i >> 4;
        int o4 = (i & 15) << 2;
        *(float4*)&ps[n][o4] = *(const float4*)(pBase + n * OO + o4);
    }
    if (t < KK * 16) {
        int k  = t >> 4;
        int o4 = (t & 15) << 2;
        *(float4*)&vs[k][o4] = *(const float4*)(g_vacc + ((size_t)b * KK + k) * OO + o4);
    }

    // Cross-phase prefetch: first hot-loop shadow pair, independent of smem.
    const __half* shBase = g_shadow + (((size_t)b * NN + n0) * OO + ob) * KK;
    uint4 ua = __ldcs((const uint4*)(shBase + (size_t)nrep * OO * KK));
    uint4 ub = __ldcs((const uint4*)(shBase + (size_t)nrep * OO * KK + KK));

    __syncthreads();

    // Delta phase: 512 dots of length 64 across 256 threads (2 each),
    // float4-vectorized; octet shuffle for row max; ed = exp(delta - max).
    {
        const float L2E = 1.4426950408889634f;
        #pragma unroll
        for (int half_ = 0; half_ < 2; half_++) {
            int id = t + half_ * 256;
            int n = id >> 3;
            int k = id & 7;
            const float4* p4 = (const float4*)&ps[n][0];
            const float4* v4 = (const float4*)&vs[k][0];
            float s = 0.f;
            #pragma unroll
            for (int j = 0; j < 16; j++) {
                float4 a = p4[j];
                float4 bq = v4[j];
                s = fmaf(a.x, bq.x, s);
                s = fmaf(a.y, bq.y, s);
                s = fmaf(a.z, bq.z, s);
                s = fmaf(a.w, bq.w, s);
            }
            float m = s;
            m = fmaxf(m, __shfl_xor_sync(0xffffffffu, m, 1));
            m = fmaxf(m, __shfl_xor_sync(0xffffffffu, m, 2));
            m = fmaxf(m, __shfl_xor_sync(0xffffffffu, m, 4));
            ds[n][k] = fast_ex2((s - m) * L2E);
        }
        __syncthreads();
    }

    float acc[KK][2];
    #pragma unroll
    for (int k = 0; k < KK; k++) { acc[k][0] = 0.f; acc[k][1] = 0.f; }

    // Hot loop: explicit depth-1 software pipeline over 8 n-steps.
    #pragma unroll
    for (int i = 0; i < NCHUNK / 8; i++) {
        const int n = nrep + i * 8;
        uint4 ca = ua, cb = ub;
        if (i < NCHUNK / 8 - 1) {
            const __half* nx = shBase + (size_t)(n + 8) * OO * KK;
            ua = __ldcs((const uint4*)nx);
            ub = __ldcs((const uint4*)(nx + KK));
        }

        float4 d0 = *(const float4*)&ds[n][0];
        float4 d1 = *(const float4*)&ds[n][4];
        float dd[KK] = {d0.x, d0.y, d0.z, d0.w, d1.x, d1.y, d1.z, d1.w};
        float2 p2 = *(const float2*)&ps[n][ob];

        float2 a01 = __half22float2(*(__half2*)&ca.x);
        float2 a23 = __half22float2(*(__half2*)&ca.y);
        float2 a45 = __half22float2(*(__half2*)&ca.z);
        float2 a67 = __half22float2(*(__half2*)&ca.w);
        float2 b01 = __half22float2(*(__half2*)&cb.x);
        float2 b23 = __half22float2(*(__half2*)&cb.y);
        float2 b45 = __half22float2(*(__half2*)&cb.z);
        float2 b67 = __half22float2(*(__half2*)&cb.w);
        float e0[KK] = {a01.x, a01.y, a23.x, a23.y, a45.x, a45.y, a67.x, a67.y};
        float e1[KK] = {b01.x, b01.y, b23.x, b23.y, b45.x, b45.y, b67.x, b67.y};

        float s0 = 0.f, s1 = 0.f;
        #pragma unroll
        for (int k = 0; k < KK; k++) {
            e0[k] *= dd[k];
            e1[k] *= dd[k];
            s0 += e0[k];
            s1 += e1[k];
        }
        float pr0 = p2.x * fast_rcp(s0);
        float pr1 = p2.y * fast_rcp(s1);
        #pragma unroll
        for (int k = 0; k < KK; k++) {
            acc[k][0] = fmaf(e0[k], pr0, acc[k][0]);
            acc[k][1] = fmaf(e1[k], pr1, acc[k][1]);
        }
    }

    __syncthreads();

    // red[(w*32 + og)*17 + kj], stride 17 -> conflict-free. 8*32*17 = 4352.
    float* red = &ps[0][0];
    {
        float* dst = red + (size_t)(nrep * 32 + og) * 17;
        #pragma unroll
        for (int k = 0; k < KK; k++) {
            dst[k * 2]     = acc[k][0];
            dst[k * 2 + 1] = acc[k][1];
        }
    }
    __syncthreads();

    #pragma unroll
    for (int id = t; id < 512; id += 256) {
        int og_ = id >> 4;
        int kj  = id & 15;
        float ssum = 0.f;
        #pragma unroll
        for (int w_ = 0; w_ < 8; w_++)
            ssum += red[(size_t)(w_ * 32 + og_) * 17 + kj];
        int k = kj >> 1;
        int j = kj & 1;
        int o = (og_ << 1) + j;
        g_zpart[(((size_t)b * NSPLIT + sp) * KK + k) * OO + o] = ssum;
    }
}

// ---------------------------------------------------------------------------
// Sum partials over splits, squash. MODE 0: Vacc = v; MODE 1: Vacc += v;
// MODE 2: write final output.
// 4 (b,k) pairs per warp, interleaved float2 loads for MLP. Grid = 64.
// ---------------------------------------------------------------------------
template <int MODE>
__global__ void __launch_bounds__(256) finish_kernel(float* __restrict__ out) {
    const int warp  = threadIdx.x >> 5;
    const int lane  = threadIdx.x & 31;
    const int pair0 = (blockIdx.x << 5) + (warp << 2);   // 4 pairs/warp

    float2 z[4];
    #pragma unroll
    for (int j = 0; j < 4; j++) { z[j].x = 0.f; z[j].y = 0.f; }

    #pragma unroll
    for (int sp = 0; sp < NSPLIT; sp++) {
        #pragma unroll
        for (int j = 0; j < 4; j++) {
            int gw = pair0 + j;
            int b = gw >> 3, k = gw & 7;
            const float2* zp = (const float2*)(g_zpart +
                (((size_t)b * NSPLIT + sp) * KK + k) * OO);
            float2 v = zp[lane];
            z[j].x += v.x;
            z[j].y += v.y;
        }
    }

    #pragma unroll
    for (int j = 0; j < 4; j++) {
        float sq = z[j].x * z[j].x + z[j].y * z[j].y;
        #pragma unroll
        for (int off = 16; off; off >>= 1)
            sq += __shfl_xor_sync(0xffffffffu, sq, off);
        float scale = sq / ((1.f + sq) * sqrtf(sq + 1e-9f));

        int gw = pair0 + j;
        int b = gw >> 3, k = gw & 7;
        size_t base = ((size_t)b * KK + k) * OO;
        float2 vv;
        vv.x = scale * z[j].x;
        vv.y = scale * z[j].y;
        if (MODE == 2) {
            ((float2*)(out + base))[lane] = vv;
        } else if (MODE == 0) {
            ((float2*)(g_vacc + base))[lane] = vv;
        } else {
            float2 old = ((float2*)(g_vacc + base))[lane];
            old.x += vv.x; old.y += vv.y;
            ((float2*)(g_vacc + base))[lane] = old;
        }
    }
}

// ---------------------------------------------------------------------------
extern "C" void kernel_launch(void* const* d_in, const int* in_sizes, int n_in,
                              void* d_out, int out_size) {
    const float* emb = (const float*)d_in[0];   // (B, N, E)
    const float* S   = (const float*)d_in[1];   // (E, O)
    const float* cc  = (const float*)d_in[2];   // (B, K, N, O)
    float* out = (float*)d_out;                 // (B, K, O)
    (void)in_sizes; (void)n_in; (void)out_size;

    route_first_kernel<<<BB * NSPLIT, 256>>>(cc, emb, S);
    finish_kernel<0><<<BB * KK / 32, 256>>>(nullptr);

    route_next_kernel<<<BB * NSPLIT, 256>>>();
    finish_kernel<1><<<BB * KK / 32, 256>>>(nullptr);

    route_next_kernel<<<BB * NSPLIT, 256>>>();
    finish_kernel<2><<<BB * KK / 32, 256>>>(out);
}

// round 17
// speedup vs baseline: 1.2090x; 1.2090x over previous
#include <cuda_runtime.h>
#include <cuda_fp16.h>
#include <cstdint>

#define BB 256
#define NN 512
#define EE 64
#define OO 64
#define KK 8
#define NSPLIT 8
#define NCHUNK (NN / NSPLIT)   // 64

// Scratch (static device allocations — allowed)
__device__ float  g_priors[BB * NN * OO];              // 33.5 MB
__device__ float  g_zpart[BB * NSPLIT * KK * OO];      // 4 MB
__device__ float  g_vacc[BB * KK * OO];                // 0.5 MB
// Shadow layout: [b][n][o][k] — 8 k-halves contiguous (16B) per (n,o).
__device__ __half g_shadow[(size_t)BB * NN * OO * KK]; // 134 MB

__device__ __forceinline__ float fast_ex2(float x) {
    float y; asm("ex2.approx.f32 %0, %1;" : "=f"(y) : "f"(x)); return y;
}
__device__ __forceinline__ float fast_rcp(float x) {
    float y; asm("rcp.approx.f32 %0, %1;" : "=f"(y) : "f"(x)); return y;
}
__device__ __forceinline__ uint32_t h2_bits(__half2 h) {
    uint32_t u; __builtin_memcpy(&u, &h, 4); return u;
}

// ---------------------------------------------------------------------------
// Iteration 1, FUSED with the priors GEMM. Writes zpart + fp16 shadow.
// ---------------------------------------------------------------------------
__global__ void __launch_bounds__(256, 5) route_first_kernel(
        const float* __restrict__ cc,
        const float* __restrict__ emb,
        const float* __restrict__ S) {
    __shared__ float buf0[64][68];   // sA (emb^T) -> ps (priors tile)
    __shared__ float buf1[64][68];   // sB (S)     -> reduction buffer

    const int t  = threadIdx.x;
    const int b  = blockIdx.x >> 3;
    const int sp = blockIdx.x & 7;
    const int n0 = sp * NCHUNK;

    // ---- Phase A: GEMM ----
    {
        const float* embBase = emb + ((size_t)b * NN + n0) * EE;
        #pragma unroll
        for (int i = t; i < 1024; i += 256) {
            int row = i >> 4;
            int e4  = (i & 15) << 2;
            float4 v = *(const float4*)(embBase + row * EE + e4);
            buf0[e4 + 0][row] = v.x; buf0[e4 + 1][row] = v.y;
            buf0[e4 + 2][row] = v.z; buf0[e4 + 3][row] = v.w;
        }
        #pragma unroll
        for (int i = t; i < 1024; i += 256) {
            int e  = i >> 4;
            int c4 = (i & 15) << 2;
            *(float4*)&buf1[e][c4] = *(const float4*)(S + e * OO + c4);
        }
        __syncthreads();

        const int tr = (t >> 4) << 2;
        const int tc = (t & 15) << 2;
        float acc[4][4];
        #pragma unroll
        for (int i = 0; i < 4; i++)
            #pragma unroll
            for (int j = 0; j < 4; j++) acc[i][j] = 0.f;

        #pragma unroll 8
        for (int e = 0; e < 64; e++) {
            float4 a = *(const float4*)&buf0[e][tr];
            float4 bq = *(const float4*)&buf1[e][tc];
            float av[4] = {a.x, a.y, a.z, a.w};
            float bv[4] = {bq.x, bq.y, bq.z, bq.w};
            #pragma unroll
            for (int i = 0; i < 4; i++)
                #pragma unroll
                for (int j = 0; j < 4; j++)
                    acc[i][j] = fmaf(av[i], bv[j], acc[i][j]);
        }
        __syncthreads();   // done reading sA before ps overwrites it

        float* outBase = g_priors + ((size_t)b * NN + n0) * OO;
        #pragma unroll
        for (int i = 0; i < 4; i++) {
            float4 v = make_float4(acc[i][0], acc[i][1], acc[i][2], acc[i][3]);
            *(float4*)&buf0[tr + i][tc] = v;                       // ps
            *(float4*)(outBase + (size_t)(tr + i) * OO + tc) = v;  // g_priors
        }
        __syncthreads();
    }

    // ---- Phase B: routing iteration 1 ----
    float (*ps)[68] = buf0;

    const int og   = t & 31;        // o-pair index
    const int ob   = og << 1;
    const int nrep = t >> 5;        // 8 n-replicas (one warp each)
    float acc[KK][2];
    #pragma unroll
    for (int k = 0; k < KK; k++) { acc[k][0] = 0.f; acc[k][1] = 0.f; }

    const float* ccBase = cc + ((size_t)b * KK * NN + n0) * OO + ob;
    __half*      shBase = g_shadow + (((size_t)b * NN + n0) * OO + ob) * KK;
    const float L2E = 1.4426950408889634f;

    #pragma unroll 2
    for (int n = nrep; n < NCHUNK; n += 8) {
        float c[KK][2];
        #pragma unroll
        for (int k = 0; k < KK; k++) {
            float2 c2 = __ldcs((const float2*)(ccBase + ((size_t)k * NN + n) * OO));
            c[k][0] = c2.x; c[k][1] = c2.y;
        }
        float2 p2 = *(const float2*)&ps[n][ob];
        float m0 = c[0][0], m1 = c[0][1];
        #pragma unroll
        for (int k = 1; k < KK; k++) {
            m0 = fmaxf(m0, c[k][0]);
            m1 = fmaxf(m1, c[k][1]);
        }
        m0 *= L2E; m1 *= L2E;
        float s0 = 0.f, s1 = 0.f;
        #pragma unroll
        for (int k = 0; k < KK; k++) {
            float e0 = fast_ex2(fmaf(c[k][0], L2E, -m0));
            float e1 = fast_ex2(fmaf(c[k][1], L2E, -m1));
            c[k][0] = e0; c[k][1] = e1;
            s0 += e0; s1 += e1;
        }
        {
            uint4 u0, u1;
            u0.x = h2_bits(__floats2half2_rn(c[0][0], c[1][0]));
            u0.y = h2_bits(__floats2half2_rn(c[2][0], c[3][0]));
            u0.z = h2_bits(__floats2half2_rn(c[4][0], c[5][0]));
            u0.w = h2_bits(__floats2half2_rn(c[6][0], c[7][0]));
            u1.x = h2_bits(__floats2half2_rn(c[0][1], c[1][1]));
            u1.y = h2_bits(__floats2half2_rn(c[2][1], c[3][1]));
            u1.z = h2_bits(__floats2half2_rn(c[4][1], c[5][1]));
            u1.w = h2_bits(__floats2half2_rn(c[6][1], c[7][1]));
            __half* dst = shBase + (size_t)n * OO * KK;
            __stcs((uint4*)dst, u0);
            __stcs((uint4*)(dst + KK), u1);
        }
        float pr0 = p2.x * fast_rcp(s0);
        float pr1 = p2.y * fast_rcp(s1);
        #pragma unroll
        for (int k = 0; k < KK; k++) {
            acc[k][0] = fmaf(c[k][0], pr0, acc[k][0]);
            acc[k][1] = fmaf(c[k][1], pr1, acc[k][1]);
        }
    }

    // Cross-warp reduction in buf1: red[(w*32 + og)*17 + kj], stride 17.
    float* red = &buf1[0][0];
    __syncthreads();
    {
        float* dst = red + (size_t)(nrep * 32 + og) * 17;
        #pragma unroll
        for (int k = 0; k < KK; k++) {
            dst[k * 2]     = acc[k][0];
            dst[k * 2 + 1] = acc[k][1];
        }
    }
    __syncthreads();

    #pragma unroll
    for (int id = t; id < 512; id += 256) {
        int og_ = id >> 4;
        int kj  = id & 15;
        float ssum = 0.f;
        #pragma unroll
        for (int w_ = 0; w_ < 8; w_++)
            ssum += red[(size_t)(w_ * 32 + og_) * 17 + kj];
        int k = kj >> 1;
        int j = kj & 1;
        int o = (og_ << 1) + j;
        g_zpart[(((size_t)b * NSPLIT + sp) * KK + k) * OO + o] = ssum;
    }
}

// ---------------------------------------------------------------------------
// Iterations 2..: read fp16 shadow E via ldcs, w ∝ E * exp(delta - max).
// 2 o's per thread: two adjacent uint4 (32B contiguous) per n-step,
// 8 n-replicas, unroll-2 (the round-11/12 proven loop shape).
// ---------------------------------------------------------------------------
__global__ void __launch_bounds__(256, 4) route_next_kernel() {
    __shared__ float ps[NCHUNK][68];   // priors chunk; reused as reduction buffer
    __shared__ float ds[NCHUNK][8];    // ed = exp(delta - rowmax)
    __shared__ float vs[KK][68];       // Vacc slice

    const int t  = threadIdx.x;
    const int b  = blockIdx.x >> 3;
    const int sp = blockIdx.x & 7;
    const int n0 = sp * NCHUNK;

    const float* pBase = g_priors + ((size_t)b * NN + n0) * OO;
    #pragma unroll
    for (int i = t; i < NCHUNK * 16; i += 256) {
        int n  = i >> 4;
        int o4 = (i & 15) << 2;
        *(float4*)&ps[n][o4] = *(const float4*)(pBase + n * OO + o4);
    }
    if (t < KK * 16) {
        int k  = t >> 4;
        int o4 = (t & 15) << 2;
        *(float4*)&vs[k][o4] = *(const float4*)(g_vacc + ((size_t)b * KK + k) * OO + o4);
    }
    __syncthreads();

    // 512 dots of length 64 across 256 threads (2 each), float4-vectorized.
    // Octet shuffle for the row max; store ed = exp(delta - max).
    {
        const float L2E = 1.4426950408889634f;
        #pragma unroll
        for (int half_ = 0; half_ < 2; half_++) {
            int id = t + half_ * 256;
            int n = id >> 3;
            int k = id & 7;
            const float4* p4 = (const float4*)&ps[n][0];
            const float4* v4 = (const float4*)&vs[k][0];
            float s = 0.f;
            #pragma unroll
            for (int j = 0; j < 16; j++) {
                float4 a = p4[j];
                float4 bq = v4[j];
                s = fmaf(a.x, bq.x, s);
                s = fmaf(a.y, bq.y, s);
                s = fmaf(a.z, bq.z, s);
                s = fmaf(a.w, bq.w, s);
            }
            float m = s;
            m = fmaxf(m, __shfl_xor_sync(0xffffffffu, m, 1));
            m = fmaxf(m, __shfl_xor_sync(0xffffffffu, m, 2));
            m = fmaxf(m, __shfl_xor_sync(0xffffffffu, m, 4));
            ds[n][k] = fast_ex2((s - m) * L2E);
        }
        __syncthreads();
    }

    const int og   = t & 31;        // o-pair index
    const int ob   = og << 1;
    const int nrep = t >> 5;        // 8 n-replicas
    float acc[KK][2];
    #pragma unroll
    for (int k = 0; k < KK; k++) { acc[k][0] = 0.f; acc[k][1] = 0.f; }

    const __half* shBase = g_shadow + (((size_t)b * NN + n0) * OO + ob) * KK;

    #pragma unroll 2
    for (int n = nrep; n < NCHUNK; n += 8) {
        const __half* src = shBase + (size_t)n * OO * KK;
        uint4 ua = __ldcs((const uint4*)src);          // o = ob
        uint4 ub = __ldcs((const uint4*)(src + KK));   // o = ob+1

        float4 d0 = *(const float4*)&ds[n][0];
        float4 d1 = *(const float4*)&ds[n][4];
        float dd[KK] = {d0.x, d0.y, d0.z, d0.w, d1.x, d1.y, d1.z, d1.w};
        float2 p2 = *(const float2*)&ps[n][ob];

        float2 a01 = __half22float2(*(__half2*)&ua.x);
        float2 a23 = __half22float2(*(__half2*)&ua.y);
        float2 a45 = __half22float2(*(__half2*)&ua.z);
        float2 a67 = __half22float2(*(__half2*)&ua.w);
        float2 b01 = __half22float2(*(__half2*)&ub.x);
        float2 b23 = __half22float2(*(__half2*)&ub.y);
        float2 b45 = __half22float2(*(__half2*)&ub.z);
        float2 b67 = __half22float2(*(__half2*)&ub.w);
        float e0[KK] = {a01.x, a01.y, a23.x, a23.y, a45.x, a45.y, a67.x, a67.y};
        float e1[KK] = {b01.x, b01.y, b23.x, b23.y, b45.x, b45.y, b67.x, b67.y};

        float s0 = 0.f, s1 = 0.f;
        #pragma unroll
        for (int k = 0; k < KK; k++) {
            e0[k] *= dd[k];
            e1[k] *= dd[k];
            s0 += e0[k];
            s1 += e1[k];
        }
        float pr0 = p2.x * fast_rcp(s0);
        float pr1 = p2.y * fast_rcp(s1);
        #pragma unroll
        for (int k = 0; k < KK; k++) {
            acc[k][0] = fmaf(e0[k], pr0, acc[k][0]);
            acc[k][1] = fmaf(e1[k], pr1, acc[k][1]);
        }
    }

    __syncthreads();

    // red[(w*32 + og)*17 + kj], stride 17 -> conflict-free. 8*32*17 = 4352.
    float* red = &ps[0][0];
    {
        float* dst = red + (size_t)(nrep * 32 + og) * 17;
        #pragma unroll
        for (int k = 0; k < KK; k++) {
            dst[k * 2]     = acc[k][0];
            dst[k * 2 + 1] = acc[k][1];
        }
    }
    __syncthreads();

    #pragma unroll
    for (int id = t; id < 512; id += 256) {
        int og_ = id >> 4;
        int kj  = id & 15;
        float ssum = 0.f;
        #pragma unroll
        for (int w_ = 0; w_ < 8; w_++)
            ssum += red[(size_t)(w_ * 32 + og_) * 17 + kj];
        int k = kj >> 1;
        int j = kj & 1;
        int o = (og_ << 1) + j;
        g_zpart[(((size_t)b * NSPLIT + sp) * KK + k) * OO + o] = ssum;
    }
}

// ---------------------------------------------------------------------------
// Sum partials over splits, squash. MODE 0: Vacc = v; MODE 1: Vacc += v;
// MODE 2: write final output.
// Grid 256, one warp per (b,k) (round-12 structure), float2 loads.
// ---------------------------------------------------------------------------
template <int MODE>
__global__ void __launch_bounds__(256) finish_kernel(float* __restrict__ out) {
    const int gw   = (blockIdx.x << 3) + (threadIdx.x >> 5);   // 0..2047
    const int lane = threadIdx.x & 31;
    const int b = gw >> 3;
    const int k = gw & 7;

    float2 z = make_float2(0.f, 0.f);
    #pragma unroll
    for (int sp = 0; sp < NSPLIT; sp++) {
        const float2* zp = (const float2*)(g_zpart +
            (((size_t)b * NSPLIT + sp) * KK + k) * OO);
        float2 v = zp[lane];
        z.x += v.x;
        z.y += v.y;
    }
    float sq = z.x * z.x + z.y * z.y;
    #pragma unroll
    for (int off = 16; off; off >>= 1)
        sq += __shfl_xor_sync(0xffffffffu, sq, off);

    float scale = sq / ((1.f + sq) * sqrtf(sq + 1e-9f));
    float2 vv = make_float2(scale * z.x, scale * z.y);

    size_t base = ((size_t)b * KK + k) * OO;
    if (MODE == 2) {
        ((float2*)(out + base))[lane] = vv;
    } else if (MODE == 0) {
        ((float2*)(g_vacc + base))[lane] = vv;
    } else {
        float2 old = ((float2*)(g_vacc + base))[lane];
        old.x += vv.x; old.y += vv.y;
        ((float2*)(g_vacc + base))[lane] = old;
    }
}

// ---------------------------------------------------------------------------
extern "C" void kernel_launch(void* const* d_in, const int* in_sizes, int n_in,
                              void* d_out, int out_size) {
    const float* emb = (const float*)d_in[0];   // (B, N, E)
    const float* S   = (const float*)d_in[1];   // (E, O)
    const float* cc  = (const float*)d_in[2];   // (B, K, N, O)
    float* out = (float*)d_out;                 // (B, K, O)
    (void)in_sizes; (void)n_in; (void)out_size;

    route_first_kernel<<<BB * NSPLIT, 256>>>(cc, emb, S);
    finish_kernel<0><<<BB * KK / 8, 256>>>(nullptr);

    route_next_kernel<<<BB * NSPLIT, 256>>>();
    finish_kernel<1><<<BB * KK / 8, 256>>>(nullptr);

    route_next_kernel<<<BB * NSPLIT, 256>>>();
    finish_kernel<2><<<BB * KK / 8, 256>>>(out);
}